// round 14
// baseline (speedup 1.0000x reference)
#include <cuda_runtime.h>
#include <cuda_fp16.h>
#include <cstdint>

#define NB 64
#define NN 22
#define NF 64
#define NO 64
#define NT 512
#define TT 4              // t-tile width per CTA
#define KF 192            // combined (k,f) contraction dim

typedef unsigned long long u64;

__device__ float d_S[2*NN*NN];     // Chebyshev supports S1, S2 (S0 = I implicit)
__device__ __half d_thT[NO*KF];    // theta^T fp16 [o][kf]

// ---------------------------------------------------------------------------
__device__ __forceinline__ uint32_t smem_u32(const void* p) {
    uint32_t a;
    asm("{ .reg .u64 t; cvta.to.shared.u64 t, %1; cvt.u32.u64 %0, t; }"
        : "=r"(a) : "l"(p));
    return a;
}
__device__ __forceinline__ void cp_async16(uint32_t dst, const void* src) {
    asm volatile("cp.async.ca.shared.global [%0], [%1], 16;"
                 :: "r"(dst), "l"(src) : "memory");
}
#define CP_COMMIT() asm volatile("cp.async.commit_group;" ::: "memory")
#define CP_WAIT2()  asm volatile("cp.async.wait_group 2;" ::: "memory")
#define CP_WAIT0()  asm volatile("cp.async.wait_group 0;" ::: "memory")

// ---------------------------------------------------------------------------
// warp-mma building blocks
// ---------------------------------------------------------------------------
#define LDSM4T(R, ADDR) \
    asm volatile("ldmatrix.sync.aligned.m8n8.x4.trans.shared.b16 {%0,%1,%2,%3}, [%4];" \
        : "=r"((R)[0]), "=r"((R)[1]), "=r"((R)[2]), "=r"((R)[3]) : "r"(ADDR))

#define LDSM4(R, ADDR) \
    asm volatile("ldmatrix.sync.aligned.m8n8.x4.shared.b16 {%0,%1,%2,%3}, [%4];" \
        : "=r"((R)[0]), "=r"((R)[1]), "=r"((R)[2]), "=r"((R)[3]) : "r"(ADDR))

#define MMA16816(D, A, B0, B1) \
    asm volatile("mma.sync.aligned.m16n8k16.row.col.f32.f16.f16.f32 " \
        "{%0,%1,%2,%3}, {%4,%5,%6,%7}, {%8,%9}, {%0,%1,%2,%3};" \
        : "+f"((D)[0]), "+f"((D)[1]), "+f"((D)[2]), "+f"((D)[3]) \
        : "r"((A)[0]), "r"((A)[1]), "r"((A)[2]), "r"((A)[3]), "r"(B0), "r"(B1))

// SMEM geometry (bytes)
#define A_STRIDE 208      // A[kf][mt]: 96 fp16 = 192 B + 16 pad
#define B_STRIDE 400      // B[o][kf]:  192 fp16 = 384 B + 16 pad
#define A_BYTES  (KF*A_STRIDE)               // 39936
#define OFF_B    A_BYTES                     // 39936
#define RING_OFF (A_BYTES + NO*B_STRIDE)     // 65536: x ring, 8 slots x 2048 B
#define DSMEM_TOTAL (RING_OFF + 8*2048)      // 81920

// ---------------------------------------------------------------------------
// K_prep: supports = softmax(relu(E E^T), axis=1); S1, S2 = 2*S1@S1 - I;
//         plus theta^T fp16 [o][kf].
// ---------------------------------------------------------------------------
__global__ void k_prep(const float* __restrict__ E, const float* __restrict__ theta) {
    __shared__ float Es[NN*NN];
    __shared__ float P[NN*NN];
    __shared__ float sup[NN*NN];
    int t = threadIdx.x;
    for (int i = t; i < NO*KF; i += 512) {
        int o = i / KF, kf = i % KF;
        d_thT[i] = __float2half(theta[kf*NO + o]);
    }
    if (t < NN*NN) Es[t] = E[t];
    __syncthreads();
    if (t < NN*NN) {
        int i = t / NN, j = t % NN;
        float s = 0.f;
        #pragma unroll
        for (int l = 0; l < NN; l++) s += Es[i*NN + l] * Es[j*NN + l];
        P[t] = fmaxf(s, 0.f);
    }
    __syncthreads();
    if (t < NN) {
        float mx = -1e30f;
        #pragma unroll
        for (int j = 0; j < NN; j++) mx = fmaxf(mx, P[t*NN + j]);
        float den = 0.f;
        #pragma unroll
        for (int j = 0; j < NN; j++) { float e = expf(P[t*NN + j] - mx); sup[t*NN + j] = e; den += e; }
        float inv = 1.f / den;
        #pragma unroll
        for (int j = 0; j < NN; j++) sup[t*NN + j] *= inv;
    }
    __syncthreads();
    if (t < NN*NN) {
        int i = t / NN, j = t % NN;
        float eye = (i == j) ? 1.f : 0.f;
        d_S[t] = sup[t];                       // S1
        float s = 0.f;
        #pragma unroll
        for (int l = 0; l < NN; l++) s += sup[i*NN + l] * sup[l*NN + j];
        d_S[NN*NN + t] = 2.f * s - eye;        // S2
    }
}

// ---------------------------------------------------------------------------
// Fused main kernel. One CTA per (b, 4-wide t-tile). 384 threads, occ 2.
// Phase 1: n-contraction, 44 heavy rows split 15/15/14 over 3 thread groups
//          (+diag in group 2), double-chunk cp.async ring, float4 coeffs.
// Phase 2: 12 warps = (mt-tile, n-half); A trans-LDSM, B non-trans LDSM.
// ---------------------------------------------------------------------------
__global__ void __launch_bounds__(384, 2) k_main(
    const float* __restrict__ x,
    const float* __restrict__ att,
    float* __restrict__ out)
{
    extern __shared__ char dsm[];
    __shared__ float4 a2q[45*6];       // [row 0..44][cc 0..5], row 44 = zeros
    __shared__ float  diag[NN];

    const int tid = threadIdx.x;
    const int b   = blockIdx.y;
    const int tt0 = blockIdx.x * TT;
    const uint32_t sbase = smem_u32(dsm);
    const uint32_t ringb = sbase + RING_OFF;
    const float*   xb    = x + (size_t)b*NN*NF*NT + tt0;
    const float*   ringf = (const float*)(dsm + RING_OFF);

    // cp.async: x chunk c = n rows {2c,2c+1}, 2048 B, slot = c&7, 128 issuers.
    const int cn2 = tid >> 6;          // 0..1 (valid tid<128)
    const int cf  = tid & 63;
    const float*   csrc0 = xb + ((size_t)cn2*NF + cf)*NT;
    const uint32_t cdst0 = ringb + (uint32_t)((cn2 << 10) | (cf << 4));

    // ---- prologue: B(theta^T) + x chunks 0..5 in 3 double-groups ----
    if (tid < 128) {
        #pragma unroll
        for (int j = 0; j < 12; j++) {
            int i = tid + j*128;
            int o = i / 24, ch = i % 24;
            cp_async16(sbase + OFF_B + o*B_STRIDE + ch*16, d_thT + o*KF + ch*8);
        }
        cp_async16(cdst0,          csrc0);
        cp_async16(cdst0 + 1*2048, csrc0 +  2*NF*NT);  CP_COMMIT();  // G0
        cp_async16(cdst0 + 2*2048, csrc0 +  4*NF*NT);
        cp_async16(cdst0 + 3*2048, csrc0 +  6*NF*NT);  CP_COMMIT();  // G1
        cp_async16(cdst0 + 4*2048, csrc0 +  8*NF*NT);
        cp_async16(cdst0 + 5*2048, csrc0 + 10*NF*NT);  CP_COMMIT();  // G2
    }

    // ---- stage a2q (float4 over n-quads) + diag ----
    for (int idx = tid; idx < 45*6; idx += 384) {
        int row = idx / 6, q = idx % 6;
        float4 v = make_float4(0.f, 0.f, 0.f, 0.f);
        if (row < 44) {
            int kk = row / 22, m = row % 22;
            float c[4];
            #pragma unroll
            for (int j = 0; j < 4; j++) {
                int n = q*4 + j;
                c[j] = (n < NN) ? d_S[kk*NN*NN + n*NN + m] * att[(b*NN + n)*NN + m]
                                : 0.f;
            }
            v = make_float4(c[0], c[1], c[2], c[3]);
        }
        a2q[idx] = v;
    }
    if (tid < NN) diag[tid] = att[(b*NN + tid)*NN + tid];

    // ---- phase 1: thread = (group, f, t-pair); group g owns rows g*15.. ----
    const int g  = tid >> 7;            // 0..2, warp-uniform
    const int f  = (tid >> 1) & 63;
    const int tp = tid & 1;
    const int r0 = g * 15;

    float a0[15], a1[15];
    #pragma unroll
    for (int i = 0; i < 15; i++) { a0[i] = 0.f; a1[i] = 0.f; }

    #pragma unroll
    for (int cc = 0; cc < 5; cc++) {
        if (tid < 128) CP_WAIT2();
        __syncthreads();
        if (tid < 128) {
            int cA = 6 + 2*cc, cB = 7 + 2*cc;
            if (cA < 11)
                cp_async16(cdst0 + (uint32_t)((cA & 7) << 11),
                           csrc0 + (size_t)(2*cA)*NF*NT);
            if (cB < 11)
                cp_async16(cdst0 + (uint32_t)((cB & 7) << 11),
                           csrc0 + (size_t)(2*cB)*NF*NT);
            CP_COMMIT();
        }
        const float* xpA = ringf + (((2*cc)   & 7) << 9);
        const float* xpB = ringf + (((2*cc+1) & 7) << 9);
        float2 xv0 = *(const float2*)(xpA +       f*4 + tp*2);   // n = 4cc
        float2 xv1 = *(const float2*)(xpA + 256 + f*4 + tp*2);   // n = 4cc+1
        float2 xv2 = *(const float2*)(xpB +       f*4 + tp*2);   // n = 4cc+2
        float2 xv3 = *(const float2*)(xpB + 256 + f*4 + tp*2);   // n = 4cc+3
        #pragma unroll
        for (int i = 0; i < 15; i++) {
            float4 aa = a2q[(r0 + i)*6 + cc];       // LDS.128 broadcast
            a0[i] = fmaf(aa.x, xv0.x, a0[i]);  a1[i] = fmaf(aa.x, xv0.y, a1[i]);
            a0[i] = fmaf(aa.y, xv1.x, a0[i]);  a1[i] = fmaf(aa.y, xv1.y, a1[i]);
            a0[i] = fmaf(aa.z, xv2.x, a0[i]);  a1[i] = fmaf(aa.z, xv2.y, a1[i]);
            a0[i] = fmaf(aa.w, xv3.x, a0[i]);  a1[i] = fmaf(aa.w, xv3.y, a1[i]);
        }
        if (g == 2) {
            // diag (k=0 plane): A row = f, value final at this chunk
            #pragma unroll
            for (int j = 0; j < 4; j++) {
                int m = 4*cc + j;
                float2 xv = (j == 0) ? xv0 : (j == 1) ? xv1 : (j == 2) ? xv2 : xv3;
                float dv = diag[m];
                __half2 h = __floats2half2_rn(dv*xv.x, dv*xv.y);
                *(uint32_t*)(dsm + f*A_STRIDE + (m*4 + tp*2)*2) = *(uint32_t*)&h;
            }
        }
    }
    // ---- tail: chunk 10 (n = 20, 21), slot 2 ----
    {
        if (tid < 128) CP_WAIT0();
        __syncthreads();
        const float* xpT = ringf + ((10 & 7) << 9);
        float2 xv0 = *(const float2*)(xpT +       f*4 + tp*2);   // n = 20
        float2 xv1 = *(const float2*)(xpT + 256 + f*4 + tp*2);   // n = 21
        #pragma unroll
        for (int i = 0; i < 15; i++) {
            float4 aa = a2q[(r0 + i)*6 + 5];
            a0[i] = fmaf(aa.x, xv0.x, a0[i]);  a1[i] = fmaf(aa.x, xv0.y, a1[i]);
            a0[i] = fmaf(aa.y, xv1.x, a0[i]);  a1[i] = fmaf(aa.y, xv1.y, a1[i]);
        }
        if (g == 2) {
            #pragma unroll
            for (int j = 0; j < 2; j++) {
                int m = 20 + j;
                float2 xv = (j == 0) ? xv0 : xv1;
                float dv = diag[m];
                __half2 h = __floats2half2_rn(dv*xv.x, dv*xv.y);
                *(uint32_t*)(dsm + f*A_STRIDE + (m*4 + tp*2)*2) = *(uint32_t*)&h;
            }
        }
    }
    // ---- store heavy rows: row r -> A[(1 + r/22)*64 + f][m*4 + tp*2] ----
    #pragma unroll
    for (int i = 0; i < 15; i++) {
        int row = r0 + i;
        if (row < 44) {
            int kk = row / 22, m = row - kk*22;
            __half2 h = __floats2half2_rn(a0[i], a1[i]);
            *(uint32_t*)(dsm + ((1 + kk)*64 + f)*A_STRIDE + (m*4 + tp*2)*2)
                = *(uint32_t*)&h;
        }
    }
    __syncthreads();

    // ---- phase 2 (R13-verified): 12 warps = (mt-tile, n-half) ----
    {
        const int w    = tid >> 5;
        const int lane = tid & 31;
        const int mt  = w >> 1;             // 0..5
        const int nh  = w & 1;              // 0..1
        const int m0b = mt * 16;
        const int n0  = nh * 32;

        const int lrow = (lane & 7) + ((lane >> 4) << 3);
        const int lga  = ((lane >> 3) & 1) * 8;
        uint32_t aA = sbase + lrow*A_STRIDE + (m0b + lga)*2;

        const int borow = ((lane >> 4) << 3) + (lane & 7);
        uint32_t aB0 = sbase + OFF_B + (n0 + borow)*B_STRIDE + ((lane >> 3) & 1)*16;
        uint32_t aB1 = aB0 + 16*B_STRIDE;

        float acc[16];
        #pragma unroll
        for (int i = 0; i < 16; i++) acc[i] = 0.f;

        #pragma unroll 4
        for (int s = 0; s < 12; s++) {
            uint32_t ah[4], b0[4], b1[4];
            LDSM4T(ah, aA  + s*(16*A_STRIDE));
            LDSM4 (b0, aB0 + s*32);
            LDSM4 (b1, aB1 + s*32);
            MMA16816(acc +  0, ah, b0[0], b0[1]);
            MMA16816(acc +  4, ah, b0[2], b0[3]);
            MMA16816(acc +  8, ah, b1[0], b1[1]);
            MMA16816(acc + 12, ah, b1[2], b1[3]);
        }

        const int tq   = (lane >> 2) & 3;
        const int mrow = lane >> 4;
        const int q2   = (lane & 3) * 2;
        #pragma unroll
        for (int j = 0; j < 4; j++) {
            #pragma unroll
            for (int i = 0; i < 2; i++) {
                int m = 4*mt + mrow + 2*i;
                if (m < NN) {
                    int o = n0 + j*8 + q2;
                    float* op = out + ((size_t)(b*NN + m)*NO + o)*NT + tt0 + tq;
                    op[0]  = fmaxf(acc[j*4 + i*2 + 0], 0.f);
                    op[NT] = fmaxf(acc[j*4 + i*2 + 1], 0.f);
                }
            }
        }
    }
}

// ---------------------------------------------------------------------------
extern "C" void kernel_launch(void* const* d_in, const int* in_sizes, int n_in,
                              void* d_out, int out_size)
{
    const float* x     = (const float*)d_in[0];   // [B,N,F_in,T]
    const float* att   = (const float*)d_in[1];   // [B,N,N]
    const float* theta = (const float*)d_in[2];   // [K,F_in,F_out]
    const float* emb   = (const float*)d_in[3];   // [N,N]
    float* out = (float*)d_out;                   // [B,N,F_out,T]

    k_prep<<<1, 512>>>(emb, theta);

    cudaFuncSetAttribute(k_main, cudaFuncAttributeMaxDynamicSharedMemorySize,
                         DSMEM_TOTAL);
    dim3 grid(NT/TT, NB);
    k_main<<<grid, 384, DSMEM_TOTAL>>>(x, att, out);
}